// round 17
// baseline (speedup 1.0000x reference)
#include <cuda_runtime.h>
#include <cuda_bf16.h>
#include <math.h>
#include <stdint.h>

#define BB 2
#define SS 2048
#define DD 1024
#define NH 16
#define NKV 4
#define HD 64
#define GATE_CH 12
#define EPSV 1e-6f
#define QKVLD 1536   // qkv buffer row stride: [q(1024) | k(256) | v(256)]

// ---------------- device scratch (allocation-free rule) ----------------
__device__ float    g_qkv[BB * SS * QKVLD];     // qkv partial 0
__device__ float    g_qkv2[BB * SS * QKVLD];    // qkv partial 1
__device__ float    g_qkv3[BB * SS * QKVLD];    // qkv partial 2
__device__ float    g_vb[(size_t)BB * NKV * 32 * 4096]; // V fragment-major tiles
__device__ float    g_xa[(size_t)32 * 64 * 2048];    // x, fragment-major A tiles
__device__ float    g_ya[(size_t)32 * 64 * 2048];    // attn out, fragment-major A tiles
__device__ float    g_wqkvT[(size_t)12 * 64 * 2048]; // Wq|Wk|Wv, fragment-major B tiles
__device__ float    g_woT[(size_t)8 * 64 * 2048];    // Wo, fragment-major B tiles
__device__ uint32_t g_qpk[BB * SS * NH * 64];   // q packed bf16 hi|lo
__device__ uint32_t g_kpk[BB * SS * NKV * 64];  // k packed bf16 hi|lo

// ---------------- helpers ----------------
__device__ __forceinline__ float to_tf32(float x) {
    float r; asm("cvt.rna.tf32.f32 %0, %1;" : "=f"(r) : "f"(x)); return r;
}
__device__ __forceinline__ uint32_t pack_bf16(float e, float o) {
    uint16_t a = __bfloat16_as_ushort(__float2bfloat16(e));
    uint16_t b = __bfloat16_as_ushort(__float2bfloat16(o));
    return ((uint32_t)b << 16) | a;
}
__device__ __forceinline__ void mma_tf32(float* d, const uint32_t* a, const uint32_t* b) {
    asm volatile(
        "mma.sync.aligned.m16n8k8.row.col.f32.tf32.tf32.f32 "
        "{%0,%1,%2,%3}, {%4,%5,%6,%7}, {%8,%9}, {%0,%1,%2,%3};\n"
        : "+f"(d[0]), "+f"(d[1]), "+f"(d[2]), "+f"(d[3])
        : "r"(a[0]), "r"(a[1]), "r"(a[2]), "r"(a[3]), "r"(b[0]), "r"(b[1]));
}
__device__ __forceinline__ void mma_bf16(float* d, const uint32_t* a, const uint32_t* b) {
    asm volatile(
        "mma.sync.aligned.m16n8k16.row.col.f32.bf16.bf16.f32 "
        "{%0,%1,%2,%3}, {%4,%5,%6,%7}, {%8,%9}, {%0,%1,%2,%3};\n"
        : "+f"(d[0]), "+f"(d[1]), "+f"(d[2]), "+f"(d[3])
        : "r"(a[0]), "r"(a[1]), "r"(a[2]), "r"(a[3]), "r"(b[0]), "r"(b[1]));
}
__device__ __forceinline__ void cp_async16(uint32_t saddr, const void* gptr) {
    asm volatile("cp.async.cg.shared.global [%0], [%1], 16;" :: "r"(saddr), "l"(gptr));
}
#define CP_COMMIT() asm volatile("cp.async.commit_group;")
#define CP_WAIT(n)  asm volatile("cp.async.wait_group %0;" :: "n"(n))

// ---------------------------------------------------------------------------
// pack_all: one launch for x (A tiles), Wq|Wk|Wv (B tiles), Wo (B tiles).
// ---------------------------------------------------------------------------
__global__ void pack_all(const float* __restrict__ x,
                         const float* __restrict__ Wq,
                         const float* __restrict__ Wk,
                         const float* __restrict__ Wv,
                         const float* __restrict__ Wo)
{
    int kt = blockIdx.x, ct = blockIdx.y;

    if (ct < 32) {
        int rt = ct;
        float* dtile = g_xa + ((size_t)rt * 64 + kt) * 2048;
        const float* s = x + (size_t)rt * 128 * 1024 + kt * 16;
        for (int q = threadIdx.x; q < 512; q += 256) {
            int gb = q >> 5;
            int g = gb >> 3, b = gb & 7;
            int lane = q & 31;
            int gid = lane >> 2, tig = lane & 3;
            const float* p = s + (size_t)(b * 16 + gid) * 1024 + g * 8 + tig;
            float4 v;
            v.x = to_tf32(p[0]);
            v.y = to_tf32(p[8 * 1024]);
            v.z = to_tf32(p[4]);
            v.w = to_tf32(p[8 * 1024 + 4]);
            *(float4*)(dtile + q * 4) = v;
        }
        return;
    }

    const float* W;
    float* dst;
    int n_src, cl, dct;
    if (ct < 44) {
        dct = ct - 32;
        dst = g_wqkvT;
        if (dct < 8)       { W = Wq; n_src = 1024; cl = dct; }
        else if (dct < 10) { W = Wk; n_src = 256;  cl = dct - 8; }
        else               { W = Wv; n_src = 256;  cl = dct - 10; }
    } else {
        dct = ct - 44;
        dst = g_woT;
        W = Wo; n_src = 1024; cl = dct;
    }

    float* dtile = dst + ((size_t)dct * 64 + kt) * 2048;
    const float* s = W + (size_t)kt * 16 * n_src + cl * 128;
    for (int q = threadIdx.x; q < 512; q += 256) {
        int plane = q >> 8;
        int q8 = q & 255;
        int gw = q8 >> 5;
        int g = gw >> 2, w = gw & 3;
        int lane = q8 & 31;
        int gid = lane >> 2, tig = lane & 3;
        const float* p = s + (size_t)(g * 8 + tig + plane * 4) * n_src + w * 32 + gid;
        float4 v;
        v.x = to_tf32(p[0]);
        v.y = to_tf32(p[8]);
        v.z = to_tf32(p[16]);
        v.w = to_tf32(p[24]);
        *(float4*)(dtile + q * 4) = v;
    }
}

// ---------------------------------------------------------------------------
// gemm_fm<SPLITK>: tf32 HMMA GEMM on fragment-major tiles (unchanged R16).
// ---------------------------------------------------------------------------
#define GFM_SMEM 98304
template<int SPLITK>
__global__ __launch_bounds__(256, 2) void gemm_fm(
    const float* __restrict__ At, const float* __restrict__ Bt,
    float* __restrict__ C0, float* __restrict__ C1, float* __restrict__ C2,
    int ldc)
{
    extern __shared__ float smg[];
    uint32_t smb = (uint32_t)__cvta_generic_to_shared(smg);
    const int tid = threadIdx.x;
    const int lane = tid & 31, wid = tid >> 5;
    const int gid = lane >> 2, tig = lane & 3;
    const int wm4 = (wid >> 2) * 4;
    const int wn5 = wid & 3;
    const int rowBase = blockIdx.y * 128, colBase = blockIdx.x * 128;

    int pofs, np;
    float* C;
    if (SPLITK == 1) { pofs = 0; np = 32; C = C0; }
    else {
        int z = blockIdx.z;
        pofs = z * 11;
        np = (z == 2) ? 10 : 11;
        C = (z == 0) ? C0 : (z == 1) ? C1 : C2;
    }

    const float* Abase = At + ((size_t)blockIdx.y * 64 + pofs * 2) * 2048 + tid * 8;
    const float* Bbase = Bt + ((size_t)blockIdx.x * 64 + pofs * 2) * 2048 + tid * 8;

#define FM_STAGE(p, s) do { \
    uint32_t _d = smb + (s) * 32768 + tid * 32; \
    const float* _a = Abase + (size_t)(p) * 4096; \
    const float* _b = Bbase + (size_t)(p) * 4096; \
    cp_async16(_d,            _a);        cp_async16(_d + 16,           _a + 4); \
    cp_async16(_d + 8192,     _a + 2048); cp_async16(_d + 8192 + 16,    _a + 2052); \
    cp_async16(_d + 16384,    _b);        cp_async16(_d + 16384 + 16,   _b + 4); \
    cp_async16(_d + 24576,    _b + 2048); cp_async16(_d + 24576 + 16,   _b + 2052); \
    CP_COMMIT(); \
} while (0)

    FM_STAGE(0, 0);
    FM_STAGE(1, 1);

    float acc[4][4][4] = {};
    for (int it = 0; it < np; it++) {
        const int s = it % 3;
        if (it + 1 < np) { CP_WAIT(1); } else { CP_WAIT(0); }
        __syncthreads();
        if (it + 2 < np) FM_STAGE(it + 2, (it + 2) % 3);

#pragma unroll
        for (int t01 = 0; t01 < 2; t01++) {
            const uint4* As4 = (const uint4*)(smg + s * 8192 + t01 * 2048);
            const uint4* Bs4 = (const uint4*)(smg + s * 8192 + 4096 + t01 * 2048);
#pragma unroll
            for (int g = 0; g < 2; g++) {
                uint4 afr[4];
#pragma unroll
                for (int mi = 0; mi < 4; mi++)
                    afr[mi] = As4[(g * 8 + wm4 + mi) * 32 + lane];
                uint4 b0 = Bs4[(g * 4 + wn5) * 32 + lane];
                uint4 b1 = Bs4[256 + (g * 4 + wn5) * 32 + lane];
                uint32_t bf[4][2] = {
                    {b0.x, b1.x}, {b0.y, b1.y}, {b0.z, b1.z}, {b0.w, b1.w}};
#pragma unroll
                for (int mi = 0; mi < 4; mi++) {
                    const uint32_t* af = (const uint32_t*)&afr[mi];
#pragma unroll
                    for (int ni = 0; ni < 4; ni++)
                        mma_tf32(acc[mi][ni], af, bf[ni]);
                }
            }
        }
    }

    const int warp_m = wm4 * 16, warp_n = wn5 * 32;
#pragma unroll
    for (int mi = 0; mi < 4; mi++) {
#pragma unroll
        for (int ni = 0; ni < 4; ni++) {
            int row = rowBase + warp_m + mi * 16 + gid;
            int col = colBase + warp_n + ni * 8 + 2 * tig;
            *(float2*)(C + (size_t)row * ldc + col) =
                make_float2(acc[mi][ni][0], acc[mi][ni][1]);
            *(float2*)(C + (size_t)(row + 8) * ldc + col) =
                make_float2(acc[mi][ni][2], acc[mi][ni][3]);
        }
    }
}

// ---------------------------------------------------------------------------
// Fused prep: rope reads p1+p2+p3 -> packed bf16 hi/lo q/k;
// vgate combines partials + gate and writes V FRAGMENT-MAJOR to g_vb.
// ---------------------------------------------------------------------------
__global__ void prep_kernel(const float* __restrict__ cosp,
                            const float* __restrict__ sinp,
                            const float* __restrict__ x,
                            const float* __restrict__ ve,
                            const float* __restrict__ Wg)
{
    int blk = blockIdx.x;
    int grp = blk % 6;
    int bs = blk / 6;
    int unit = threadIdx.x >> 6;
    int d = threadIdx.x & 63;
    int hh = grp * 4 + unit;

    if (hh >= NH + NKV) {
        int kvh = hh - (NH + NKV);
        const float* xr = x + (size_t)bs * DD;
        float g = 0.f;
#pragma unroll
        for (int c = 0; c < GATE_CH; c++) g += xr[c] * Wg[c * NKV + kvh];
        g = 3.f / (1.f + __expf(-g));
        size_t off = (size_t)bs * QKVLD + 1280 + kvh * HD + d;
        float v = g_qkv[off] + g_qkv2[off] + g_qkv3[off]
                + g * ve[(size_t)bs * (NKV * HD) + kvh * HD + d];
        // fragment-major V write
        int b = bs / SS, s = bs % SS;
        int tile = s >> 6, l = s & 63;
        int kgrp = l >> 3, r2 = l & 7;
        int plane = r2 >> 2, tg = r2 & 3;
        int nif = d >> 3, gd = d & 7;
        int nhalf = nif >> 2, nil = nif & 3;
        size_t base = ((size_t)((b * NKV + kvh) * 32 + tile)) * 4096;
        g_vb[base + ((kgrp * 2 + plane) * 2 + nhalf) * 128 + (gd * 4 + tg) * 4 + nil]
            = to_tf32(v);
        return;
    }

    int s = bs % SS;
    size_t base = (size_t)bs * QKVLD + ((hh < NH) ? hh * HD : 1024 + (hh - NH) * HD);

    int half = d & 31;
    float c  = cosp[s * 32 + half];
    float sn = sinp[s * 32 + half];
    float x1 = g_qkv[base + half]      + g_qkv2[base + half]      + g_qkv3[base + half];
    float x2 = g_qkv[base + half + 32] + g_qkv2[base + half + 32] + g_qkv3[base + half + 32];
    float rot = (d < 32) ? (x1 * c + x2 * sn) : (-x1 * sn + x2 * c);

    __shared__ float red[4][2];
    float v = rot * rot;
#pragma unroll
    for (int o = 16; o > 0; o >>= 1) v += __shfl_xor_sync(0xffffffffu, v, o);
    if ((d & 31) == 0) red[unit][d >> 5] = v;
    __syncthreads();
    float total = red[unit][0] + red[unit][1];
    float r = rsqrtf(total * (1.f / HD) + EPSV) * 1.2f;
    float val = rot * r;
    if (hh < NH) val *= 0.125f;

    float hif = __bfloat162float(__float2bfloat16(val));
    float lof = val - hif;
    float val_o = __shfl_down_sync(0xffffffffu, val, 1);
    float lof_o = __shfl_down_sync(0xffffffffu, lof, 1);

    if ((d & 1) == 0) {
        uint32_t hp = pack_bf16(val, val_o);
        uint32_t lp = pack_bf16(lof, lof_o);
        uint32_t* out = (hh < NH)
            ? &g_qpk[((size_t)bs * NH + hh) * 64]
            : &g_kpk[((size_t)bs * NKV + (hh - NH)) * 64];
        out[d >> 1]        = hp;
        out[32 + (d >> 1)] = lp;
    }
}

// ---------------------------------------------------------------------------
// Tensor-core flash attention, 128 queries/CTA, 8 warps, register softmax.
// Fragment-major V (LDS.128), fragment-major P (LDS.128), interior-tile
// fast path (no mask ALU). Heavy-first CTA order.
// smem: K[2][TILEF] | V[2][4096] | Ss[128*ATS]
// ---------------------------------------------------------------------------
#define ATS 68
#define TILEF (64 * ATS)
#define VOFF (2 * TILEF)
#define SSOFF (2 * TILEF + 8192)
__global__ __launch_bounds__(256, 2) void attn_tc(const int* __restrict__ winp)
{
    const int win = *winp;
    int bid = blockIdx.x;
    int qt = 15 - (bid & 15);
    int bh = bid >> 4;
    int h = bh % NH;
    int b = bh / NH;
    int q0 = qt * 128;
    int kvh = h / (NH / NKV);

    const int tid = threadIdx.x;
    const int lane = tid & 31;
    const int warp = tid >> 5;
    const int wrow = warp * 16;
    const int gid = lane >> 2;
    const int tig = lane & 3;

    extern __shared__ float sm[];
    uint32_t* Khl0 = (uint32_t*)sm;
    float* Ss = sm + SSOFF;
    float* Pb = Ss + warp * 1024;    // per-warp fragment-major P (8 ks x 128)
    uint32_t smbase = (uint32_t)__cvta_generic_to_shared(sm);

    const int st_r  = tid >> 4;
    const int st_c4 = (tid & 15) * 4;

    {
        uint32_t* Qs = (uint32_t*)Ss;
        for (int i = tid; i < 128 * 16; i += 256) {
            int r = i >> 4;
            int c4 = (i & 15) * 4;
            *(uint4*)&Qs[r * ATS + c4] =
                *(const uint4*)(g_qpk + ((size_t)(b * SS + q0 + r) * NH + h) * 64 + c4);
        }
    }
    __syncthreads();

    uint32_t ahi[4][4], alo[4][4];
    {
        const uint32_t* Qs = (const uint32_t*)Ss;
#pragma unroll
        for (int ks = 0; ks < 4; ks++) {
            int cb = ks * 8 + tig;
            ahi[ks][0] = Qs[(wrow + gid) * ATS + cb];
            ahi[ks][1] = Qs[(wrow + gid + 8) * ATS + cb];
            ahi[ks][2] = Qs[(wrow + gid) * ATS + cb + 4];
            ahi[ks][3] = Qs[(wrow + gid + 8) * ATS + cb + 4];
            alo[ks][0] = Qs[(wrow + gid) * ATS + 32 + cb];
            alo[ks][1] = Qs[(wrow + gid + 8) * ATS + 32 + cb];
            alo[ks][2] = Qs[(wrow + gid) * ATS + 32 + cb + 4];
            alo[ks][3] = Qs[(wrow + gid + 8) * ATS + 32 + cb + 4];
        }
    }
    __syncthreads();   // done reading Qs before P-buffer writes reuse Ss

    float m0 = -1e30f, m1 = -1e30f, lsum0 = 0.f, lsum1 = 0.f;
    float oacc[8][4] = {};

    int kmin = q0 - win + 1;
    if (kmin < 0) kmin = 0;
    int t0 = kmin >> 6;
    int t1 = (q0 + 127) >> 6;

#define AT_STAGE(tt, bf) do { \
    int _kb = (tt) << 6; \
    const uint32_t* _ks = g_kpk + ((size_t)(b * SS + _kb + st_r) * NKV + kvh) * 64 + st_c4; \
    uint32_t _kd = smbase + ((bf) * TILEF + st_r * ATS + st_c4) * 4; \
    _Pragma("unroll") \
    for (int _j = 0; _j < 4; _j++) \
        cp_async16(_kd + _j * 16 * ATS * 4, _ks + (size_t)_j * 16 * NKV * 64); \
    const float* _vs = g_vb + ((size_t)((b * NKV + kvh) * 32 + (tt))) * 4096 + tid * 16; \
    uint32_t _vd = smbase + (VOFF + (bf) * 4096 + tid * 16) * 4; \
    _Pragma("unroll") \
    for (int _j = 0; _j < 4; _j++) \
        cp_async16(_vd + _j * 16, _vs + _j * 4); \
    CP_COMMIT(); \
} while (0)

    AT_STAGE(t0, 0);

    for (int t = t0; t <= t1; t++) {
        int kb = t << 6;
        const int buf = (t - t0) & 1;
        CP_WAIT(0);
        __syncthreads();
        if (t < t1) AT_STAGE(t + 1, buf ^ 1);

        bool active = (kb <= q0 + wrow + 15) && (kb + 63 >= q0 + wrow - win + 1);
        if (active) {
            const uint32_t* Khl = Khl0 + buf * TILEF;
            const float4* vf4 = (const float4*)(sm + VOFF + buf * 4096);

            float accS[8][4] = {};
#pragma unroll
            for (int ks = 0; ks < 4; ks++) {
#pragma unroll
                for (int ni = 0; ni < 8; ni++) {
                    const uint32_t* kr = &Khl[(ni * 8 + gid) * ATS + ks * 8 + tig];
                    uint32_t bh2[2] = { kr[0],  kr[4] };
                    uint32_t bl2[2] = { kr[32], kr[36] };
                    mma_bf16(accS[ni], ahi[ks], bh2);
                    mma_bf16(accS[ni], alo[ks], bh2);
                    mma_bf16(accS[ni], ahi[ks], bl2);
                }
            }

            int qpos0 = q0 + wrow + gid;
            int qpos1 = qpos0 + 8;
            bool fullv = (kb + 63 <= q0 + wrow) && (kb >= q0 + wrow + 15 - win + 1);
            float mx0 = -1e30f, mx1 = -1e30f;
            if (fullv) {
#pragma unroll
                for (int ni = 0; ni < 8; ni++) {
                    mx0 = fmaxf(mx0, fmaxf(accS[ni][0], accS[ni][1]));
                    mx1 = fmaxf(mx1, fmaxf(accS[ni][2], accS[ni][3]));
                }
            } else {
#pragma unroll
                for (int ni = 0; ni < 8; ni++) {
#pragma unroll
                    for (int j = 0; j < 4; j++) {
                        int kpos = kb + ni * 8 + 2 * tig + (j & 1);
                        int qp = (j < 2) ? qpos0 : qpos1;
                        bool ok = (kpos <= qp) && (kpos >= qp - win + 1);
                        float s = ok ? accS[ni][j] : -1e30f;
                        accS[ni][j] = s;
                        if (j < 2) mx0 = fmaxf(mx0, s);
                        else       mx1 = fmaxf(mx1, s);
                    }
                }
            }
            mx0 = fmaxf(mx0, __shfl_xor_sync(0xffffffffu, mx0, 1));
            mx0 = fmaxf(mx0, __shfl_xor_sync(0xffffffffu, mx0, 2));
            mx1 = fmaxf(mx1, __shfl_xor_sync(0xffffffffu, mx1, 1));
            mx1 = fmaxf(mx1, __shfl_xor_sync(0xffffffffu, mx1, 2));

            float mnew0 = fmaxf(m0, mx0), mnew1 = fmaxf(m1, mx1);
            bool dead0 = (mnew0 <= -1e20f), dead1 = (mnew1 <= -1e20f);
            float scale0 = dead0 ? 1.f : __expf(m0 - mnew0);
            float scale1 = dead1 ? 1.f : __expf(m1 - mnew1);

            // exp + row sum + fragment-major P write
            float rs0 = 0.f, rs1 = 0.f;
#pragma unroll
            for (int ni = 0; ni < 8; ni++) {
#pragma unroll
                for (int j = 0; j < 4; j++) {
                    bool lo = (j < 2);
                    float p = lo ? (dead0 ? 0.f : __expf(accS[ni][j] - mnew0))
                                 : (dead1 ? 0.f : __expf(accS[ni][j] - mnew1));
                    if (lo) rs0 += p; else rs1 += p;
                    int cw = 2 * tig + (j & 1);
                    int tr = cw & 3;
                    int slot = ((cw >> 2) << 1) + (j >> 1);
                    Pb[ni * 128 + (gid * 4 + tr) * 4 + slot] = to_tf32(p);
                }
            }
            rs0 += __shfl_xor_sync(0xffffffffu, rs0, 1);
            rs0 += __shfl_xor_sync(0xffffffffu, rs0, 2);
            rs1 += __shfl_xor_sync(0xffffffffu, rs1, 1);
            rs1 += __shfl_xor_sync(0xffffffffu, rs1, 2);

            m0 = mnew0; m1 = mnew1;
            lsum0 = lsum0 * scale0 + rs0;
            lsum1 = lsum1 * scale1 + rs1;

#pragma unroll
            for (int ni = 0; ni < 8; ni++) {
                oacc[ni][0] *= scale0; oacc[ni][1] *= scale0;
                oacc[ni][2] *= scale1; oacc[ni][3] *= scale1;
            }
            __syncwarp();

            // PV: vectorized fragment loads
#pragma unroll
            for (int ks = 0; ks < 8; ks++) {
                float4 paf = *(const float4*)(Pb + ks * 128 + lane * 4);
                const uint32_t* pa = (const uint32_t*)&paf;
                float4 v00 = vf4[ks * 128 + lane];
                float4 v01 = vf4[ks * 128 + 32 + lane];
                float4 v10 = vf4[ks * 128 + 64 + lane];
                float4 v11 = vf4[ks * 128 + 96 + lane];
                const uint32_t* p00 = (const uint32_t*)&v00;
                const uint32_t* p01 = (const uint32_t*)&v01;
                const uint32_t* p10 = (const uint32_t*)&v10;
                const uint32_t* p11 = (const uint32_t*)&v11;
#pragma unroll
                for (int ni = 0; ni < 4; ni++) {
                    uint32_t vb[2] = { p00[ni], p10[ni] };
                    mma_tf32(oacc[ni], pa, vb);
                }
#pragma unroll
                for (int ni = 0; ni < 4; ni++) {
                    uint32_t vb[2] = { p01[ni], p11[ni] };
                    mma_tf32(oacc[4 + ni], pa, vb);
                }
            }
        }
    }

    float li0 = 1.f / lsum0;
    float li1 = 1.f / lsum1;

    __syncthreads();
#pragma unroll
    for (int ni = 0; ni < 8; ni++) {
        int c0 = ni * 8 + 2 * tig;
        Ss[(wrow + gid) * ATS + c0]         = oacc[ni][0] * li0;
        Ss[(wrow + gid) * ATS + c0 + 1]     = oacc[ni][1] * li0;
        Ss[(wrow + gid + 8) * ATS + c0]     = oacc[ni][2] * li1;
        Ss[(wrow + gid + 8) * ATS + c0 + 1] = oacc[ni][3] * li1;
    }
    __syncthreads();

    int rtile = b * 16 + qt;
#pragma unroll
    for (int tl = 0; tl < 4; tl++) {
        float* dtile = g_ya + ((size_t)rtile * 64 + h * 4 + tl) * 2048;
        for (int q = tid; q < 512; q += 256) {
            int gb = q >> 5;
            int g2 = gb >> 3, b2 = gb & 7;
            int ln = q & 31;
            int gd = ln >> 2, tg = ln & 3;
            const float* sp = &Ss[(b2 * 16 + gd) * ATS + tl * 16 + g2 * 8 + tg];
            float4 v;
            v.x = to_tf32(sp[0]);
            v.y = to_tf32(sp[8 * ATS]);
            v.z = to_tf32(sp[4]);
            v.w = to_tf32(sp[8 * ATS + 4]);
            *(float4*)(dtile + q * 4) = v;
        }
    }
}

// ---------------------------------------------------------------------------
extern "C" void kernel_launch(void* const* d_in, const int* in_sizes, int n_in,
                              void* d_out, int out_size)
{
    const float* x    = (const float*)d_in[0];
    const float* ve   = (const float*)d_in[1];
    const float* cosp = (const float*)d_in[2];
    const float* sinp = (const float*)d_in[3];
    const float* Wq   = (const float*)d_in[4];
    const float* Wk   = (const float*)d_in[5];
    const float* Wv   = (const float*)d_in[6];
    const float* Wo   = (const float*)d_in[7];
    const float* Wg   = (const float*)d_in[8];
    const int*   win  = (const int*)d_in[9];
    float* out = (float*)d_out;

    float *pqkv, *pqkv2, *pqkv3, *pxa, *pya, *pwqkvT, *pwoT;
    cudaGetSymbolAddress((void**)&pqkv, g_qkv);
    cudaGetSymbolAddress((void**)&pqkv2, g_qkv2);
    cudaGetSymbolAddress((void**)&pqkv3, g_qkv3);
    cudaGetSymbolAddress((void**)&pxa, g_xa);
    cudaGetSymbolAddress((void**)&pya, g_ya);
    cudaGetSymbolAddress((void**)&pwqkvT, g_wqkvT);
    cudaGetSymbolAddress((void**)&pwoT, g_woT);

    // single merged packing launch
    pack_all<<<dim3(64, 52), 256>>>(x, Wq, Wk, Wv, Wo);

    cudaFuncSetAttribute(gemm_fm<3>, cudaFuncAttributeMaxDynamicSharedMemorySize, GFM_SMEM);
    cudaFuncSetAttribute(gemm_fm<1>, cudaFuncAttributeMaxDynamicSharedMemorySize, GFM_SMEM);

    // fused QKV projection, split-K=3
    gemm_fm<3><<<dim3(12, 32, 3), 256, GFM_SMEM>>>(pxa, pwqkvT, pqkv, pqkv2, pqkv3, QKVLD);

    // fused partial combine + v-gate (fragment-major V) + RoPE/RMSNorm + packing
    prep_kernel<<<BB * SS * 6, 256>>>(cosp, sinp, x, ve, Wg);

    // flash attention (fragment-major V/P, interior fast path)
    {
        int smem = (2 * TILEF + 8192 + 128 * ATS) * sizeof(float);   // 102400 B
        cudaFuncSetAttribute(attn_tc, cudaFuncAttributeMaxDynamicSharedMemorySize, smem);
        attn_tc<<<BB * NH * (SS / 128), 256, smem>>>(win);
    }

    // output projection (single wave, reads fragment-major g_ya directly)
    gemm_fm<1><<<dim3(8, 32, 1), 256, GFM_SMEM>>>(pya, pwoT, out, nullptr, nullptr, DD);
}